// round 12
// baseline (speedup 1.0000x reference)
#include <cuda_runtime.h>
#include <math.h>
#include <stdint.h>

#define NTOK 8192
#define DD   512
#define FFD  2048
#define GG   102
#define GAM  0.5f
#define NEGV (-1e9f)
#define QKSCALE 0.044194173824159216f   // 1/sqrt(512)

// Global "GEMM-ready" layout: within each row's 16-word chunk,
// stored[g*4 + j] = orig[4*j + g]. Staging = identity 16B copies (cp.async),
// one LDS.128 of group g yields k = {g, g+4, g+8, g+12} for the mma.

// ================= scratch (device globals; no allocation allowed) =========
static __device__ float g_dropx [NTOK * DD];
static __device__ float g_dropxr[NTOK * DD];     // tf32-rounded, permuted
static __device__ float g_q [NTOK * DD];
static __device__ float g_k [NTOK * DD];
static __device__ float g_qf[NTOK * DD];
static __device__ float g_kf[NTOK * DD];
static __device__ float g_vt[NTOK * DD];          // V^T rounded+permuted [DD, NTOK]
static __device__ float g_t0[NTOK * DD];
static __device__ float g_h1 [NTOK * DD];
static __device__ float g_h1r[NTOK * DD];         // rounded+permuted
static __device__ float g_h2 [NTOK * DD];
static __device__ float g_h2r[NTOK * DD];
static __device__ float g_ffb[NTOK * FFD];        // rounded+permuted
static __device__ float g_Sr[(size_t)NTOK * NTOK];   // permuted cols
static __device__ float g_Sf[(size_t)NTOK * NTOK];   // permuted cols
static __device__ float g_rinv[NTOK];
static __device__ float g_wt[11 * DD * DD + DD * FFD + FFD * DD];  // rounded+permuted

// ================= helpers =================================================
__device__ __forceinline__ float rnd_tf32(float f) {
    uint32_t u;
    asm("cvt.rna.tf32.f32 %0, %1;" : "=r"(u) : "f"(f));
    return __uint_as_float(u);
}
__device__ __forceinline__ int pi16(int c) {   // permuted index within row
    return (c & ~15) | ((c & 3) << 2) | ((c & 15) >> 2);
}
__device__ __forceinline__ uint32_t smem_u32(const void* p) {
    uint32_t a;
    asm("{ .reg .u64 t; cvta.to.shared.u64 t, %1; cvt.u32.u64 %0, t; }" : "=r"(a) : "l"(p));
    return a;
}
#define CP_ASYNC16(dst, src) \
    asm volatile("cp.async.cg.shared.global [%0], [%1], 16;" :: "r"(dst), "l"(src) : "memory")
#define CP_COMMIT()  asm volatile("cp.async.commit_group;" ::: "memory")
#define CP_WAIT1()   asm volatile("cp.async.wait_group 1;" ::: "memory")

__device__ __forceinline__ void mma_tf32(float* d, uint32_t a0, uint32_t a1,
                                         uint32_t a2, uint32_t a3,
                                         uint32_t b0, uint32_t b1) {
    asm volatile(
        "mma.sync.aligned.m16n8k8.row.col.f32.tf32.tf32.f32 "
        "{%0,%1,%2,%3}, {%4,%5,%6,%7}, {%8,%9}, {%0,%1,%2,%3};"
        : "+f"(d[0]), "+f"(d[1]), "+f"(d[2]), "+f"(d[3])
        : "r"(a0), "r"(a1), "r"(a2), "r"(a3), "r"(b0), "r"(b1));
}

// ================ tf32 NT GEMM: C[M,Nc] = A[M,K] @ B[Nc,K]^T ================
// A, B in GEMM-ready permuted layout (tf32-rounded). CTA 128x128, 128 threads,
// 4 warps (2m x 2n), warp 64x64. 3-stage cp.async pipeline, K=32 per stage
// (two k-halves of 16 per stage, no barrier between halves).
// EPI: 0 plain, 1 +bias, 2 +bias+GELU, 3 row-scale rs[m], 4 score mask+scale
// RND: round output to tf32. PERM: write output in permuted layout.
template <int EPI, int RND, int PERM>
__global__ void __launch_bounds__(128, 2) k_mma_gemm(
    const float* __restrict__ A, const float* __restrict__ B, float* __restrict__ C,
    int M, int Nc, int K,
    const float* __restrict__ bias, const float* __restrict__ rs,
    const int* __restrict__ mask)
{
    extern __shared__ uint32_t sm[];
    uint32_t* As = sm;                 // [3][128*32]
    uint32_t* Bs = sm + 3 * 4096;      // [3][128*32]

    const int tid = threadIdx.x;       // 0..127
    const int wid = tid >> 5;
    const int lane = tid & 31;
    const int wm = wid >> 1;
    const int wn = wid & 1;
    const int bx = blockIdx.x, by = blockIdx.y;

    const float* srcA = A + (size_t)(by * 128 + tid) * K;
    const float* srcB = B + (size_t)(bx * 128 + tid) * K;
    const uint32_t sa = smem_u32(As) + tid * 128;   // 32 words/row
    const uint32_t sb = smem_u32(Bs) + tid * 128;

    const int nch = K >> 5;            // K multiple of 32 for all our shapes

    // prologue: stages 0..1
#pragma unroll
    for (int c = 0; c < 2; c++) {
        const float* pa = srcA + c * 32;
        const float* pb = srcB + c * 32;
        uint32_t da = sa + (uint32_t)c * 16384u;
        uint32_t db = sb + (uint32_t)c * 16384u;
#pragma unroll
        for (int q = 0; q < 8; q++) CP_ASYNC16(da + q * 16, pa + q * 4);
#pragma unroll
        for (int q = 0; q < 8; q++) CP_ASYNC16(db + q * 16, pb + q * 4);
        CP_COMMIT();
    }

    float acc[4][8][4];
#pragma unroll
    for (int i = 0; i < 4; i++)
#pragma unroll
        for (int j = 0; j < 8; j++)
#pragma unroll
            for (int q = 0; q < 4; q++) acc[i][j][q] = 0.0f;

    for (int c = 0; c < nch; ++c) {
        CP_WAIT1();
        __syncthreads();
        const int s = c - (c / 3) * 3;           // c % 3
        const uint32_t* as = As + s * 4096;
        const uint32_t* bs = Bs + s * 4096;

        // issue chunk c+2 into slot (c+2)%3 == slot read at iter c-1
        // (safe: barrier above means all warps are past iter c-1 reads)
        if (c + 2 < nch) {
            const int cn = c + 2;
            const int sn = cn - (cn / 3) * 3;
            const float* pa = srcA + cn * 32;
            const float* pb = srcB + cn * 32;
            uint32_t da = sa + (uint32_t)sn * 16384u;
            uint32_t db = sb + (uint32_t)sn * 16384u;
#pragma unroll
            for (int q = 0; q < 8; q++) CP_ASYNC16(da + q * 16, pa + q * 4);
#pragma unroll
            for (int q = 0; q < 8; q++) CP_ASYNC16(db + q * 16, pb + q * 4);
        }
        CP_COMMIT();

        // two k-halves, no barrier between them
#pragma unroll
        for (int kh = 0; kh < 2; kh++) {
            uint4 fb[8];
#pragma unroll
            for (int nt = 0; nt < 8; nt++) {
                int nl = wn * 64 + nt * 8 + (lane >> 2);
                fb[nt] = *(const uint4*)&bs[nl * 32 + kh * 16 + ((lane & 3) << 2)];
            }
#pragma unroll
            for (int mt = 0; mt < 4; mt++) {
                const int rl = wm * 64 + mt * 16 + (lane >> 2);
                uint4 fa0 = *(const uint4*)&as[rl * 32 + kh * 16 + ((lane & 3) << 2)];
                uint4 fa1 = *(const uint4*)&as[(rl + 8) * 32 + kh * 16 + ((lane & 3) << 2)];
#pragma unroll
                for (int nt = 0; nt < 8; nt++) {
                    mma_tf32(acc[mt][nt], fa0.x, fa1.x, fa0.y, fa1.y, fb[nt].x, fb[nt].y);
                    mma_tf32(acc[mt][nt], fa0.z, fa1.z, fa0.w, fa1.w, fb[nt].z, fb[nt].w);
                }
            }
        }
    }

    // ---- epilogue ----
    const int col_b = bx * 128 + wn * 64 + (lane & 3) * 2;
#pragma unroll
    for (int mt = 0; mt < 4; mt++) {
#pragma unroll
        for (int h = 0; h < 2; h++) {
            int row = by * 128 + wm * 64 + mt * 16 + (lane >> 2) + h * 8;
            float rsv = (EPI == 3) ? rs[row] : 1.0f;
            float* Cr = C + (size_t)row * Nc;
            const int* Mr = (EPI == 4) ? (mask + (size_t)row * Nc) : nullptr;
#pragma unroll
            for (int nt = 0; nt < 8; nt++) {
                int col = col_b + nt * 8;   // even, col%16 <= 14
                float v0 = acc[mt][nt][h * 2 + 0];
                float v1 = acc[mt][nt][h * 2 + 1];
                if (EPI == 1 || EPI == 2) { v0 += bias[col]; v1 += bias[col + 1]; }
                if (EPI == 2) {
                    v0 = 0.5f * v0 * (1.0f + erff(v0 * 0.7071067811865475f));
                    v1 = 0.5f * v1 * (1.0f + erff(v1 * 0.7071067811865475f));
                }
                if (EPI == 3) { v0 *= rsv; v1 *= rsv; }
                if (EPI == 4) {
                    int2 mk = *(const int2*)(Mr + col);
                    v0 = mk.x ? NEGV : v0 * QKSCALE;
                    v1 = mk.y ? NEGV : v1 * QKSCALE;
                }
                if (RND) { v0 = rnd_tf32(v0); v1 = rnd_tf32(v1); }
                if (PERM) {
                    Cr[pi16(col)] = v0;
                    Cr[pi16(col + 1)] = v1;
                } else {
                    float2 o; o.x = v0; o.y = v1;
                    *(float2*)(Cr + col) = o;
                }
            }
        }
    }
}

// ========== transpose ALL 13 weights (rounded, permuted) in ONE launch ======
struct TPList {
    const float* src[13];
    float*       dst[13];
    int          R[13];
    int          C[13];
};
__global__ void k_transpose_all(TPList L) {
    int z = blockIdx.z;
    int R = L.R[z], C = L.C[z];
    int r0 = blockIdx.y * 32, c0 = blockIdx.x * 32;
    if (r0 >= R || c0 >= C) return;
    const float* in = L.src[z];
    float* out = L.dst[z];
    __shared__ float t[32][33];
    int x = threadIdx.x, y = threadIdx.y;
    for (int i = y; i < 32; i += 8)
        t[i][x] = in[(size_t)(r0 + i) * C + c0 + x];
    __syncthreads();
    for (int i = y; i < 32; i += 8)
        out[(size_t)(c0 + i) * R + pi16(r0 + x)] = rnd_tf32(t[x][i]);
}

// ===== drop_x build (normal + rounded-permuted) + x_init gather =============
__global__ void k_drop(const float* __restrict__ x, const int* __restrict__ idx,
                       float* __restrict__ dx, float* __restrict__ dxr,
                       float* __restrict__ out_init) {
    int r = blockIdx.x;
    const float* xr = x + (size_t)r * DD;
    float* dr  = dx  + (size_t)r * DD;
    float* drr = dxr + (size_t)r * DD;
    for (int c = threadIdx.x; c < DD; c += blockDim.x) {
        float v = xr[c];
        dr[c] = v;
        drr[pi16(c)] = rnd_tf32(v);
    }
    __syncthreads();
    for (int g = threadIdx.x; g < GG; g += blockDim.x) {
        int c = idx[r * GG + g];
        out_init[r * GG + g] = xr[c];
        dr[c] = 0.0f;
        drr[pi16(c)] = 0.0f;
    }
}

// ====== dual softmax combine (in-place; layout-invariant per row) ===========
__global__ void k_softmax(float* __restrict__ Sr, const float* __restrict__ Sf,
                          float* __restrict__ rinv) {
    int r = blockIdx.x, tid = threadIdx.x;
    float* sr = Sr + (size_t)r * NTOK;
    const float* sf = Sf + (size_t)r * NTOK;
    __shared__ float red[256];
    float m = -3.4e38f;
    for (int j = tid * 4; j < NTOK; j += 1024) {
        float4 a = *(const float4*)&sr[j];
        float4 b = *(const float4*)&sf[j];
        m = fmaxf(m, fmaxf(fmaxf(a.x, a.y), fmaxf(a.z, a.w)));
        m = fmaxf(m, fmaxf(fmaxf(b.x, b.y), fmaxf(b.z, b.w)));
    }
    red[tid] = m; __syncthreads();
    for (int s = 128; s > 0; s >>= 1) {
        if (tid < s) red[tid] = fmaxf(red[tid], red[tid + s]);
        __syncthreads();
    }
    m = red[0]; __syncthreads();
    float sum = 0.0f;
    for (int j = tid * 4; j < NTOK; j += 1024) {
        float4 a = *(const float4*)&sr[j];
        float4 b = *(const float4*)&sf[j];
        float4 p;
        p.x = expf(a.x - m) + GAM * expf(b.x - m);
        p.y = expf(a.y - m) + GAM * expf(b.y - m);
        p.z = expf(a.z - m) + GAM * expf(b.z - m);
        p.w = expf(a.w - m) + GAM * expf(b.w - m);
        sum += p.x + p.y + p.z + p.w;
        p.x = rnd_tf32(p.x); p.y = rnd_tf32(p.y);
        p.z = rnd_tf32(p.z); p.w = rnd_tf32(p.w);
        *(float4*)&sr[j] = p;
    }
    red[tid] = sum; __syncthreads();
    for (int s = 128; s > 0; s >>= 1) {
        if (tid < s) red[tid] += red[tid + s];
        __syncthreads();
    }
    if (tid == 0) rinv[r] = 1.0f / red[0];
}

// ===== residual add + LayerNorm (normal out + rounded-permuted out) =========
__global__ void k_addln(const float* __restrict__ a, const float* __restrict__ b,
                        const float* __restrict__ g, const float* __restrict__ bb,
                        float* __restrict__ out, float* __restrict__ outr) {
    int r = blockIdx.x, tid = threadIdx.x;
    __shared__ float s1[128], s2[128];
    const float* ar = a + (size_t)r * DD;
    const float* br = b + (size_t)r * DD;
    float4 va = *(const float4*)&ar[tid * 4];
    float4 vb = *(const float4*)&br[tid * 4];
    float v0 = va.x + vb.x, v1 = va.y + vb.y, v2 = va.z + vb.z, v3 = va.w + vb.w;
    s1[tid] = v0 + v1 + v2 + v3;
    s2[tid] = v0 * v0 + v1 * v1 + v2 * v2 + v3 * v3;
    __syncthreads();
    for (int s = 64; s > 0; s >>= 1) {
        if (tid < s) { s1[tid] += s1[tid + s]; s2[tid] += s2[tid + s]; }
        __syncthreads();
    }
    float mu = s1[0] * (1.0f / DD);
    float var = s2[0] * (1.0f / DD) - mu * mu;
    float rstd = rsqrtf(var + 1e-5f);
    int c = tid * 4;
    float4 o;
    o.x = (v0 - mu) * rstd * g[c + 0] + bb[c + 0];
    o.y = (v1 - mu) * rstd * g[c + 1] + bb[c + 1];
    o.z = (v2 - mu) * rstd * g[c + 2] + bb[c + 2];
    o.w = (v3 - mu) * rstd * g[c + 3] + bb[c + 3];
    *(float4*)&out[(size_t)r * DD + c] = o;
    float* orr = outr + (size_t)r * DD;
    orr[pi16(c + 0)] = rnd_tf32(o.x);
    orr[pi16(c + 1)] = rnd_tf32(o.y);
    orr[pi16(c + 2)] = rnd_tf32(o.z);
    orr[pi16(c + 3)] = rnd_tf32(o.w);
}

// ================= final gather =============================================
__global__ void k_gather(const float* __restrict__ H, const int* __restrict__ idx,
                         float* __restrict__ out) {
    int r = blockIdx.x;
    for (int g = threadIdx.x; g < GG; g += blockDim.x)
        out[r * GG + g] = H[(size_t)r * DD + idx[r * GG + g]];
}

// ================= host side ================================================
#define GEMM_SMEM (3 * 4096 * 2 * 4)   // 98304 bytes

template <int EPI, int RND, int PERM>
static void mma_gemm(const float* A, const float* B, float* C, int M, int Nc, int K,
                     const float* bias = nullptr, const float* rs = nullptr,
                     const int* mask = nullptr) {
    static bool configured = false;
    if (!configured) {
        cudaFuncSetAttribute(k_mma_gemm<EPI, RND, PERM>,
                             cudaFuncAttributeMaxDynamicSharedMemorySize, GEMM_SMEM);
        configured = true;
    }
    dim3 g(Nc / 128, M / 128);
    k_mma_gemm<EPI, RND, PERM><<<g, 128, GEMM_SMEM>>>(A, B, C, M, Nc, K, bias, rs, mask);
}

static void run_attention(const float* hr,
                          const float* Wqr_t, const float* Wkr_t,
                          const float* Wqf_t, const float* Wkf_t, const float* Wv_t,
                          const int* rmask, const int* fmask,
                          float* q, float* k, float* qf, float* kf, float* vt,
                          float* Sr, float* Sf, float* rinv, float* outbuf) {
    mma_gemm<0, 1, 1>(hr, Wqr_t, q,  NTOK, DD, DD);
    mma_gemm<0, 1, 1>(hr, Wkr_t, k,  NTOK, DD, DD);
    mma_gemm<0, 1, 1>(hr, Wqf_t, qf, NTOK, DD, DD);
    mma_gemm<0, 1, 1>(hr, Wkf_t, kf, NTOK, DD, DD);
    // V^T computed directly: vt[d, tok] = sum_k WvT[d,k] * hr[tok,k]
    mma_gemm<0, 1, 1>(Wv_t, hr, vt, DD, NTOK, DD);
    mma_gemm<4, 0, 1>(q,  k,  Sr, NTOK, NTOK, DD, nullptr, nullptr, rmask);
    mma_gemm<4, 0, 1>(qf, kf, Sf, NTOK, NTOK, DD, nullptr, nullptr, fmask);
    k_softmax<<<NTOK, 256>>>(Sr, Sf, rinv);
    mma_gemm<3, 0, 0>(Sr, vt, outbuf, NTOK, DD, NTOK, nullptr, rinv);
}

extern "C" void kernel_launch(void* const* d_in, const int* in_sizes, int n_in,
                              void* d_out, int out_size) {
    const float* x    = (const float*)d_in[0];
    const int*   idx  = (const int*)  d_in[1];
    const int*   rmsk = (const int*)  d_in[2];
    const int*   fmsk = (const int*)  d_in[3];
    const float* W[11] = {
        (const float*)d_in[4],  (const float*)d_in[5],  (const float*)d_in[6],
        (const float*)d_in[7],  (const float*)d_in[8],  (const float*)d_in[9],
        (const float*)d_in[10], (const float*)d_in[11], (const float*)d_in[12],
        (const float*)d_in[13], (const float*)d_in[24]  // head_W last
    };
    const float* fW1 = (const float*)d_in[14];
    const float* fb1 = (const float*)d_in[15];
    const float* fW2 = (const float*)d_in[16];
    const float* fb2 = (const float*)d_in[17];
    const float* l1g = (const float*)d_in[18];
    const float* l1b = (const float*)d_in[19];
    const float* l2g = (const float*)d_in[20];
    const float* l2b = (const float*)d_in[21];
    const float* l3g = (const float*)d_in[22];
    const float* l3b = (const float*)d_in[23];
    const float* hb  = (const float*)d_in[25];

    float* out       = (float*)d_out;
    float* out_init  = out;
    float* out_recon = out + (size_t)NTOK * GG;

    float *dropx, *dropxr, *q, *k, *qf, *kf, *vt, *t0;
    float *h1, *h1r, *h2, *h2r, *ffb, *Sr, *Sf, *rinv, *wt;
    cudaGetSymbolAddress((void**)&dropx,  g_dropx);
    cudaGetSymbolAddress((void**)&dropxr, g_dropxr);
    cudaGetSymbolAddress((void**)&q,  g_q);
    cudaGetSymbolAddress((void**)&k,  g_k);
    cudaGetSymbolAddress((void**)&qf, g_qf);
    cudaGetSymbolAddress((void**)&kf, g_kf);
    cudaGetSymbolAddress((void**)&vt, g_vt);
    cudaGetSymbolAddress((void**)&t0, g_t0);
    cudaGetSymbolAddress((void**)&h1,  g_h1);
    cudaGetSymbolAddress((void**)&h1r, g_h1r);
    cudaGetSymbolAddress((void**)&h2,  g_h2);
    cudaGetSymbolAddress((void**)&h2r, g_h2r);
    cudaGetSymbolAddress((void**)&ffb, g_ffb);
    cudaGetSymbolAddress((void**)&Sr, g_Sr);
    cudaGetSymbolAddress((void**)&Sf, g_Sf);
    cudaGetSymbolAddress((void**)&rinv, g_rinv);
    cudaGetSymbolAddress((void**)&wt, g_wt);

    // transposed (rounded, permuted) weight destinations
    float* Wt[11];
    for (int i = 0; i < 11; i++) Wt[i] = wt + (size_t)i * DD * DD;
    float* fW1t = wt + (size_t)11 * DD * DD;            // [FFD, DD]
    float* fW2t = fW1t + (size_t)DD * FFD;              // [DD, FFD]

    // ---- launch 0: all 13 weight transposes in one kernel ----
    TPList L;
    for (int i = 0; i < 11; i++) {
        L.src[i] = W[i]; L.dst[i] = Wt[i]; L.R[i] = DD; L.C[i] = DD;
    }
    L.src[11] = fW1; L.dst[11] = fW1t; L.R[11] = DD;  L.C[11] = FFD;
    L.src[12] = fW2; L.dst[12] = fW2t; L.R[12] = FFD; L.C[12] = DD;
    k_transpose_all<<<dim3(64, 64, 13), dim3(32, 8)>>>(L);

    // ---- launch 1: drop_x (+rounded permuted) + x_init ----
    k_drop<<<NTOK, 128>>>(x, idx, dropx, dropxr, out_init);

    // encoder attention
    run_attention(dropxr, Wt[0], Wt[1], Wt[2], Wt[3], Wt[4], rmsk, fmsk,
                  q, k, qf, kf, vt, Sr, Sf, rinv, t0);
    k_addln<<<NTOK, 128>>>(t0, dropx, l1g, l1b, h1, h1r);

    // feed-forward
    mma_gemm<2, 1, 1>(h1r, fW1t, ffb, NTOK, FFD, DD, fb1);
    mma_gemm<1, 0, 0>(ffb, fW2t, t0, NTOK, DD, FFD, fb2);
    k_addln<<<NTOK, 128>>>(t0, h1, l2g, l2b, h2, h2r);

    // decoder attention
    run_attention(h2r, Wt[5], Wt[6], Wt[7], Wt[8], Wt[9], rmsk, fmsk,
                  q, k, qf, kf, vt, Sr, Sf, rinv, t0);
    k_addln<<<NTOK, 128>>>(t0, h2, l3g, l3b, h1, h1r);

    // head + x_recon gather
    mma_gemm<1, 0, 0>(h1r, Wt[10], t0, NTOK, DD, DD, hb);
    k_gather<<<NTOK, 128>>>(t0, idx, out_recon);
}